// round 14
// baseline (speedup 1.0000x reference)
#include <cuda_runtime.h>
#include <cuda_bf16.h>
#include <cstdint>

#define N_NODES 50000
#define N_EDGES 400000
#define HIDDEN 128
#define DEPTH 3
#define NT_E (N_EDGES / 128)          // 3125 (init tiles)
#define NT_C (N_EDGES / 64)           // 6250 (conv tiles)

typedef unsigned long long ull;
typedef uint32_t u32;

// ---------------- scratch ----------------
__device__ __nv_bfloat16 g_hhi[(size_t)N_EDGES * HIDDEN];
__device__ __nv_bfloat16 g_hlo[(size_t)N_EDGES * HIDDEN];
__device__ __nv_bfloat16 g_nhi[(size_t)N_EDGES * HIDDEN];
__device__ __nv_bfloat16 g_nlo[(size_t)N_EDGES * HIDDEN];
__device__ float g_aggA[(size_t)N_NODES * HIDDEN];
__device__ float g_aggB[(size_t)N_NODES * HIDDEN];
__device__ float g_xw  [(size_t)N_NODES * HIDDEN];
__device__ float g_aggW[(size_t)N_NODES * HIDDEN];

// ================= helpers =================
__device__ __forceinline__ u32 smem_u32(const void* p) {
    u32 a;
    asm("{ .reg .u64 t; cvta.to.shared.u64 t, %1; cvt.u32.u64 %0, t; }" : "=r"(a) : "l"(p));
    return a;
}

__device__ __forceinline__ void split4(float4 v, ull& hi, ull& lo) {
    __nv_bfloat16 h0 = __float2bfloat16_rn(v.x), h1 = __float2bfloat16_rn(v.y);
    __nv_bfloat16 h2 = __float2bfloat16_rn(v.z), h3 = __float2bfloat16_rn(v.w);
    __nv_bfloat16 l0 = __float2bfloat16_rn(v.x - __bfloat162float(h0));
    __nv_bfloat16 l1 = __float2bfloat16_rn(v.y - __bfloat162float(h1));
    __nv_bfloat16 l2 = __float2bfloat16_rn(v.z - __bfloat162float(h2));
    __nv_bfloat16 l3 = __float2bfloat16_rn(v.w - __bfloat162float(h3));
    u32 ha = (u32)__bfloat16_as_ushort(h0) | ((u32)__bfloat16_as_ushort(h1) << 16);
    u32 hb = (u32)__bfloat16_as_ushort(h2) | ((u32)__bfloat16_as_ushort(h3) << 16);
    u32 la = (u32)__bfloat16_as_ushort(l0) | ((u32)__bfloat16_as_ushort(l1) << 16);
    u32 lb = (u32)__bfloat16_as_ushort(l2) | ((u32)__bfloat16_as_ushort(l3) << 16);
    hi = (ull)ha | ((ull)hb << 32);
    lo = (ull)la | ((ull)lb << 32);
}

__device__ __forceinline__ void split2(float x, float y, u32& hi, u32& lo) {
    __nv_bfloat16 hx = __float2bfloat16_rn(x), hy = __float2bfloat16_rn(y);
    __nv_bfloat16 lx = __float2bfloat16_rn(x - __bfloat162float(hx));
    __nv_bfloat16 ly = __float2bfloat16_rn(y - __bfloat162float(hy));
    hi = (u32)__bfloat16_as_ushort(hx) | ((u32)__bfloat16_as_ushort(hy) << 16);
    lo = (u32)__bfloat16_as_ushort(lx) | ((u32)__bfloat16_as_ushort(ly) << 16);
}

__device__ __forceinline__ void ldsm4(u32* r, u32 addr) {
    asm volatile("ldmatrix.sync.aligned.m8n8.x4.shared.b16 {%0,%1,%2,%3}, [%4];"
                 : "=r"(r[0]), "=r"(r[1]), "=r"(r[2]), "=r"(r[3]) : "r"(addr));
}

__device__ __forceinline__ void mma16816(float* d, const u32* a, const u32* b) {
    asm volatile("mma.sync.aligned.m16n8k16.row.col.f32.bf16.bf16.f32 "
                 "{%0,%1,%2,%3}, {%4,%5,%6,%7}, {%8,%9}, {%0,%1,%2,%3};"
                 : "+f"(d[0]), "+f"(d[1]), "+f"(d[2]), "+f"(d[3])
                 : "r"(a[0]), "r"(a[1]), "r"(a[2]), "r"(a[3]), "r"(b[0]), "r"(b[1]));
}

__device__ __forceinline__ void cp16(u32 dst, const void* src) {
    asm volatile("cp.async.cg.shared.global [%0], [%1], 16;" :: "r"(dst), "l"(src));
}
#define CP_COMMIT() asm volatile("cp.async.commit_group;" ::: "memory")
#define CP_WAIT0()  asm volatile("cp.async.wait_group 0;" ::: "memory")

__device__ __forceinline__ void red2(float* p, float a, float b) {
    asm volatile("red.global.add.v2.f32 [%0], {%1, %2};" :: "l"(p), "f"(a), "f"(b) : "memory");
}

// generic 16-rows x 128-cols mainloop
template<int KSTEPS, int SBv>
__device__ __forceinline__ void mma_loop(u32 aH, u32 aL, u32 bH, u32 bL, float acc[16][4]) {
    for (int ks = 0; ks < KSTEPS; ++ks) {
        u32 ah[4], al[4];
        ldsm4(ah, aH + ks * 32);
        ldsm4(al, aL + ks * 32);
        #pragma unroll
        for (int p = 0; p < 8; ++p) {
            u32 bh[4], bl[4];
            ldsm4(bh, bH + p * (16 * SBv * 2) + ks * 32);
            ldsm4(bl, bL + p * (16 * SBv * 2) + ks * 32);
            mma16816(acc[2*p],   ah, bh);
            mma16816(acc[2*p+1], ah, bh + 2);
            mma16816(acc[2*p],   ah, bl);
            mma16816(acc[2*p+1], ah, bl + 2);
            mma16816(acc[2*p],   al, bh);
            mma16816(acc[2*p+1], al, bh + 2);
        }
    }
}

__device__ __forceinline__ void store_raw(const float acc[16][4], float* out,
                                          int row_base, int g, int tq, int rmax) {
    int r0 = row_base + g, r1 = row_base + g + 8;
    float* o0 = out + (size_t)r0 * 128;
    float* o1 = out + (size_t)r1 * 128;
    bool w0 = r0 < rmax, w1 = r1 < rmax;
    #pragma unroll
    for (int p = 0; p < 16; ++p) {
        int c0 = p * 8 + tq * 2;
        if (w0) *(float2*)(o0 + c0) = make_float2(acc[p][0], acc[p][1]);
        if (w1) *(float2*)(o1 + c0) = make_float2(acc[p][2], acc[p][3]);
    }
}

__device__ __forceinline__ void store_relu(const float acc[16][4], const float* bs,
                                           float* out, int row_base, int g, int tq, int rmax) {
    int r0 = row_base + g, r1 = row_base + g + 8;
    float* o0 = out + (size_t)r0 * 128;
    float* o1 = out + (size_t)r1 * 128;
    bool w0 = r0 < rmax, w1 = r1 < rmax;
    #pragma unroll
    for (int p = 0; p < 16; ++p) {
        int c0 = p * 8 + tq * 2;
        if (w0) *(float2*)(o0 + c0) = make_float2(fmaxf(acc[p][0] + bs[c0], 0.f),
                                                  fmaxf(acc[p][1] + bs[c0+1], 0.f));
        if (w1) *(float2*)(o1 + c0) = make_float2(fmaxf(acc[p][2] + bs[c0], 0.f),
                                                  fmaxf(acc[p][3] + bs[c0+1], 0.f));
    }
}

// ============ k_ngemm<KD,SBv>: persistent; out[M,128] = A[M,KD] @ W[KD,128] ============
template<int KD, int SBv>
__global__ __launch_bounds__(256) void k_ngemm(
    const float* __restrict__ A, const float* __restrict__ W,
    float* __restrict__ out, int M, int ntiles)
{
    extern __shared__ char smem[];
    const int M1 = 128 * SBv * 2;
    char* Ah = smem; char* Al = smem + M1; char* Bh = smem + 2*M1; char* Bl = smem + 3*M1;
    u32 sbase = smem_u32(smem);
    int tid = threadIdx.x, wid = tid >> 5, lane = tid & 31;
    int g = lane >> 2, tq = lane & 3;

    // W^T hi/lo: convert ONCE per CTA
    {
        int n = tid >> 1, half = tid & 1;
        #pragma unroll
        for (int c = 0; c < KD/8; ++c) {
            int k = half * (KD/2) + c * 4;
            float4 wv = make_float4(__ldg(&W[(k+0)*128 + n]), __ldg(&W[(k+1)*128 + n]),
                                    __ldg(&W[(k+2)*128 + n]), __ldg(&W[(k+3)*128 + n]));
            ull hi, lo; split4(wv, hi, lo);
            u32 off = (u32)(n * SBv + k) * 2;
            *(ull*)(Bh + off) = hi; *(ull*)(Bl + off) = lo;
        }
    }

    int a_row = lane & 15, a_col = (lane >> 4) * 8;
    u32 aH = sbase + (u32)((wid*16 + a_row) * SBv + a_col) * 2;
    u32 aL = aH + M1;
    int b_row = (lane & 7) + ((lane >> 4) & 1) * 8;
    int b_col = ((lane >> 3) & 1) * 8;
    u32 bH = sbase + 2*M1 + (u32)(b_row * SBv + b_col) * 2;
    u32 bL = bH + M1;

    for (int tile = blockIdx.x; tile < ntiles; tile += gridDim.x) {
        __syncthreads();   // previous MMA done reading A
        {
            int n = tid >> 1, half = tid & 1;
            int node = tile * 128 + n;
            #pragma unroll
            for (int c = 0; c < KD/8; ++c) {
                int k = half * (KD/2) + c * 4;
                float4 av = (node < M) ? *(const float4*)(A + (size_t)node * KD + k)
                                       : make_float4(0.f, 0.f, 0.f, 0.f);
                ull hi, lo; split4(av, hi, lo);
                u32 off = (u32)(n * SBv + k) * 2;
                *(ull*)(Ah + off) = hi; *(ull*)(Al + off) = lo;
            }
        }
        __syncthreads();

        float acc[16][4];
        #pragma unroll
        for (int p = 0; p < 16; ++p) { acc[p][0]=0; acc[p][1]=0; acc[p][2]=0; acc[p][3]=0; }
        mma_loop<KD/16, SBv>(aH, aL, bH, bL, acc);
        store_raw(acc, out, tile * 128 + wid * 16, g, tq, M);
    }
}

// ============ k_init2: h0 = relu(ea@W1b + xW[row] + b); writes bf16 hi/lo + reds ======
#define ISB 24
#define IMAT (128 * ISB * 2)
#define I_BIAS 0
#define I_A    512
#define I_B    (512 + 2*IMAT)
#define I_TOT  (512 + 4*IMAT)

__global__ __launch_bounds__(256) void k_init2(
    const float* __restrict__ ea, const int* __restrict__ row,
    const int* __restrict__ col,
    const float* __restrict__ Wb, const float* __restrict__ b,
    const float* __restrict__ xw,
    __nv_bfloat16* __restrict__ ohi, __nv_bfloat16* __restrict__ olo,
    float* __restrict__ aggn)
{
    extern __shared__ char smem[];
    u32 sbase = smem_u32(smem);
    int tid = threadIdx.x, wid = tid >> 5, lane = tid & 31;
    int g = lane >> 2, tq = lane & 3;
    int tile = blockIdx.x;

    int e0 = tile * 128 + wid * 16 + g;
    int e1 = e0 + 8;
    int r0i = __ldg(&row[e0]), r1i = __ldg(&row[e1]);
    int c0i = __ldg(&col[e0]), c1i = __ldg(&col[e1]);

    float* bs = (float*)(smem + I_BIAS);
    if (tid < 128) bs[tid] = __ldg(&b[tid]);
    {
        int n = tid >> 1, half = tid & 1;
        int e = tile * 128 + n;
        #pragma unroll
        for (int c = 0; c < 2; ++c) {
            int k = half * 8 + c * 4;
            float4 wv = make_float4(__ldg(&Wb[(k+0)*128 + n]), __ldg(&Wb[(k+1)*128 + n]),
                                    __ldg(&Wb[(k+2)*128 + n]), __ldg(&Wb[(k+3)*128 + n]));
            ull hi, lo; split4(wv, hi, lo);
            u32 off = (u32)(n * ISB + k) * 2;
            *(ull*)(smem + I_B + off) = hi; *(ull*)(smem + I_B + IMAT + off) = lo;
            float4 av = *(const float4*)(ea + (size_t)e * 16 + k);
            split4(av, hi, lo);
            *(ull*)(smem + I_A + off) = hi; *(ull*)(smem + I_A + IMAT + off) = lo;
        }
    }
    __syncthreads();

    int a_row = lane & 15, a_col = (lane >> 4) * 8;
    u32 aH = sbase + I_A + (u32)((wid*16 + a_row) * ISB + a_col) * 2;
    u32 aL = aH + IMAT;
    int b_row = (lane & 7) + ((lane >> 4) & 1) * 8;
    int b_col = ((lane >> 3) & 1) * 8;
    u32 bH = sbase + I_B + (u32)(b_row * ISB + b_col) * 2;
    u32 bL = bH + IMAT;

    float acc[16][4];
    #pragma unroll
    for (int p = 0; p < 16; ++p) { acc[p][0]=0; acc[p][1]=0; acc[p][2]=0; acc[p][3]=0; }
    mma_loop<1, ISB>(aH, aL, bH, bL, acc);

    const float* x0 = xw + (size_t)r0i * 128;
    const float* x1 = xw + (size_t)r1i * 128;
    float* ag0 = aggn + (size_t)c0i * 128;
    float* ag1 = aggn + (size_t)c1i * 128;
    u32* oh = (u32*)ohi; u32* ol = (u32*)olo;
    #pragma unroll
    for (int p = 0; p < 16; ++p) {
        int c = p * 8 + tq * 2;
        float2 g0 = __ldg((const float2*)(x0 + c));
        float2 g1 = __ldg((const float2*)(x1 + c));
        float v0x = fmaxf(acc[p][0] + g0.x + bs[c],   0.f);
        float v0y = fmaxf(acc[p][1] + g0.y + bs[c+1], 0.f);
        float v1x = fmaxf(acc[p][2] + g1.x + bs[c],   0.f);
        float v1y = fmaxf(acc[p][3] + g1.y + bs[c+1], 0.f);
        u32 hi, lo;
        split2(v0x, v0y, hi, lo);
        oh[(size_t)e0*64 + c/2] = hi; ol[(size_t)e0*64 + c/2] = lo;
        split2(v1x, v1y, hi, lo);
        oh[(size_t)e1*64 + c/2] = hi; ol[(size_t)e1*64 + c/2] = lo;
        red2(ag0 + c, v0x, v0y);
        red2(ag1 + c, v1x, v1y);
    }
}

// ============ k_conv3: N-split half-tiles, 2 CTA/SM, double-buffered A ======
// CTA b: tile t = b>>1, n-half = b&1. 64 edges x 64 cols per CTA.
#define CSB 136
#define CB_MAT (64 * CSB * 2)      // 17408 (B half: 64 n-rows)
#define CA_MAT (64 * CSB * 2)      // 17408 (A: 64 edge-rows)
#define C3_BIAS 0
#define C3_B    512                // Bhi, Blo
#define C3_A    (512 + 2*CB_MAT)   // 35328: stages s*(2*CA_MAT): [Ahi, Alo]
#define C3_TOT  (C3_A + 4*CA_MAT)  // 104960

template<int STORE_H>
__global__ __launch_bounds__(256, 2) void k_conv3(
    const __nv_bfloat16* __restrict__ hhi, const __nv_bfloat16* __restrict__ hlo,
    const int* __restrict__ row, const int* __restrict__ col,
    const float* __restrict__ W,
    const float* __restrict__ b, const float* __restrict__ aggW,
    __nv_bfloat16* __restrict__ ohi, __nv_bfloat16* __restrict__ olo,
    float* __restrict__ aggn)
{
    extern __shared__ char smem[];
    u32 sbase = smem_u32(smem);
    int tid = threadIdx.x, wid = tid >> 5, lane = tid & 31;
    int w_m = wid >> 1, w_n = wid & 1;       // w_m: 16-row group; w_n: 32-col half of 64
    int g = lane >> 2, tq = lane & 3;
    int nhalf = blockIdx.x & 1;
    int t0 = blockIdx.x >> 1;
    int tstep = (int)(gridDim.x >> 1);

    float* bs = (float*)(smem + C3_BIAS);
    if (tid < 128) bs[tid] = __ldg(&b[tid]);
    {   // B half = W^T[nhalf*64 .. +64) hi/lo
        int nl = tid >> 2, kq = (tid & 3) * 32;
        int n = nhalf * 64 + nl;
        #pragma unroll
        for (int c = 0; c < 8; ++c) {
            int k = kq + c * 4;
            float4 wv = make_float4(__ldg(&W[(k+0)*128 + n]), __ldg(&W[(k+1)*128 + n]),
                                    __ldg(&W[(k+2)*128 + n]), __ldg(&W[(k+3)*128 + n]));
            ull hi, lo; split4(wv, hi, lo);
            u32 off = (u32)(nl * CSB + k) * 2;
            *(ull*)(smem + C3_B + off) = hi; *(ull*)(smem + C3_B + CB_MAT + off) = lo;
        }
    }
    __syncthreads();

    int a_row = lane & 15, a_col = (lane >> 4) * 8;
    u32 a_off = (u32)((w_m*16 + a_row) * CSB + a_col) * 2;
    int b_row = (lane & 7) + ((lane >> 4) & 1) * 8;
    int b_col = ((lane >> 3) & 1) * 8;
    u32 b_base = sbase + C3_B + (u32)(b_row * CSB + b_col) * 2;

    int fr = tid >> 4, fc = tid & 15;

    // prologue: stage 0 <- tile t0
    {
        #pragma unroll
        for (int k2 = 0; k2 < 4; ++k2) {
            int r = fr + k2 * 16;
            u32 d = sbase + C3_A + r * (CSB*2) + fc * 16;
            size_t go = ((size_t)(t0 * 64 + r)) * 128 + fc * 8;
            cp16(d, hhi + go);
            cp16(d + CA_MAT, hlo + go);
        }
    }
    CP_COMMIT();

    int s = 0;
    for (int t = t0; t < NT_C; t += tstep) {
        // epilogue prefetch (no smem dependency)
        int e0 = t * 64 + w_m * 16 + g;
        int e1 = e0 + 8;
        int r0i = __ldg(&row[e0]), r1i = __ldg(&row[e1]);
        int c0i = __ldg(&col[e0]), c1i = __ldg(&col[e1]);
        const float2* aw0 = (const float2*)(aggW + (size_t)r0i * 128);
        const float2* aw1 = (const float2*)(aggW + (size_t)r1i * 128);
        float* ag0 = aggn + (size_t)c0i * 128;
        float* ag1 = aggn + (size_t)c1i * 128;
        float2 pg0[4], pg1[4];
        #pragma unroll
        for (int p = 0; p < 4; ++p) {
            int ci = (nhalf * 64 + w_n * 32 + (p >> 1) * 16 + (p & 1) * 8 + tq * 2) >> 1;
            pg0[p] = __ldg(aw0 + ci);
            pg1[p] = __ldg(aw1 + ci);
        }

        CP_WAIT0();
        __syncthreads();   // stage s ready; all warps done with prev iter's MMA on s^1

        // issue next fill into s^1 (flies under MMA + epilogue)
        int tn = t + tstep;
        if (tn < NT_C) {
            #pragma unroll
            for (int k2 = 0; k2 < 4; ++k2) {
                int r = fr + k2 * 16;
                u32 d = sbase + C3_A + (s ^ 1) * 2 * CA_MAT + r * (CSB*2) + fc * 16;
                size_t go = ((size_t)(tn * 64 + r)) * 128 + fc * 8;
                cp16(d, hhi + go);
                cp16(d + CA_MAT, hlo + go);
            }
        }
        CP_COMMIT();

        // MMA: 16 rows x 32 cols
        u32 aH = sbase + C3_A + s * 2 * CA_MAT + a_off;
        u32 aL = aH + CA_MAT;
        float acc[4][4];
        #pragma unroll
        for (int p = 0; p < 4; ++p) { acc[p][0]=0; acc[p][1]=0; acc[p][2]=0; acc[p][3]=0; }
        for (int ks = 0; ks < 8; ++ks) {
            u32 ah[4], al[4];
            ldsm4(ah, aH + ks * 32);
            ldsm4(al, aL + ks * 32);
            #pragma unroll
            for (int p2 = 0; p2 < 2; ++p2) {
                u32 bh[4], bl[4];
                u32 ba = b_base + (u32)(w_n*32 + p2*16) * (CSB*2) + ks * 32;
                ldsm4(bh, ba);
                ldsm4(bl, ba + CB_MAT);
                mma16816(acc[2*p2],   ah, bh);
                mma16816(acc[2*p2+1], ah, bh + 2);
                mma16816(acc[2*p2],   ah, bl);
                mma16816(acc[2*p2+1], ah, bl + 2);
                mma16816(acc[2*p2],   al, bh);
                mma16816(acc[2*p2+1], al, bh + 2);
            }
        }

        // epilogue: h'[e] = relu(aggW[row[e]] - hW[e^1] + b); red into aggn
        u32* oh = (u32*)ohi; u32* ol = (u32*)olo;
        #pragma unroll
        for (int p = 0; p < 4; ++p) {
            int c = nhalf * 64 + w_n * 32 + (p >> 1) * 16 + (p & 1) * 8 + tq * 2;
            float r0x = __shfl_xor_sync(0xffffffffu, acc[p][0], 4);
            float r0y = __shfl_xor_sync(0xffffffffu, acc[p][1], 4);
            float r1x = __shfl_xor_sync(0xffffffffu, acc[p][2], 4);
            float r1y = __shfl_xor_sync(0xffffffffu, acc[p][3], 4);
            float v0x = fmaxf(pg0[p].x - r0x + bs[c],   0.f);
            float v0y = fmaxf(pg0[p].y - r0y + bs[c+1], 0.f);
            float v1x = fmaxf(pg1[p].x - r1x + bs[c],   0.f);
            float v1y = fmaxf(pg1[p].y - r1y + bs[c+1], 0.f);
            if (STORE_H) {
                u32 hi, lo;
                split2(v0x, v0y, hi, lo);
                oh[(size_t)e0*64 + c/2] = hi; ol[(size_t)e0*64 + c/2] = lo;
                split2(v1x, v1y, hi, lo);
                oh[(size_t)e1*64 + c/2] = hi; ol[(size_t)e1*64 + c/2] = lo;
            }
            red2(ag0 + c, v0x, v0y);
            red2(ag1 + c, v1x, v1y);
        }
        s ^= 1;
    }
}

// ============ k_final: out = relu([x ; s] @ W2 + b2), K=192 ============
#define SBF 200
#define MATF (128 * SBF * 2)
#define FSM_BIAS 0
#define FSM_AHI  512
#define FSM_ALO  (FSM_AHI + MATF)
#define FSM_BHI  (FSM_ALO + MATF)
#define FSM_BLO  (FSM_BHI + MATF)
#define FSM_TOT  (FSM_BLO + MATF)

__global__ __launch_bounds__(256, 1) void k_final_mma(
    const float* __restrict__ x, const float* __restrict__ agg,
    const float* __restrict__ W, const float* __restrict__ b, float* __restrict__ out)
{
    extern __shared__ char smem[];
    u32 sbase = smem_u32(smem);
    int tid = threadIdx.x, wid = tid >> 5, lane = tid & 31;
    int g = lane >> 2, tq = lane & 3;

    float* bs = (float*)(smem + FSM_BIAS);
    if (tid < 128) bs[tid] = __ldg(&b[tid]);
    {
        int n = tid >> 1, kh = (tid & 1) * 96;
        char* Bh = smem + FSM_BHI; char* Bl = smem + FSM_BLO;
        #pragma unroll
        for (int c = 0; c < 24; ++c) {
            int k = kh + c * 4;
            float4 v = make_float4(__ldg(&W[(k+0)*128 + n]), __ldg(&W[(k+1)*128 + n]),
                                   __ldg(&W[(k+2)*128 + n]), __ldg(&W[(k+3)*128 + n]));
            ull hi, lo; split4(v, hi, lo);
            u32 off = (u32)(n * SBF + k) * 2;
            *(ull*)(Bh + off) = hi; *(ull*)(Bl + off) = lo;
        }
    }
    __syncthreads();

    int a_row = lane & 15, a_col = (lane >> 4) * 8;
    u32 aH = sbase + FSM_AHI + (u32)((wid * 16 + a_row) * SBF + a_col) * 2;
    u32 aL = aH + MATF;
    int b_row = (lane & 7) + ((lane >> 4) & 1) * 8;
    int b_col = ((lane >> 3) & 1) * 8;
    u32 bH = sbase + FSM_BHI + (u32)(b_row * SBF + b_col) * 2;
    u32 bL = bH + MATF;

    const float4* x4   = (const float4*)x;
    const float4* agg4 = (const float4*)agg;
    char* Ah = smem + FSM_AHI; char* Al = smem + FSM_ALO;
    const int NT = (N_NODES + 127) / 128;

    for (int tile = blockIdx.x; tile < NT; tile += gridDim.x) {
        {
            int r = tid >> 1, half = tid & 1;
            int n = tile * 128 + r;
            #pragma unroll
            for (int c = 0; c < 24; ++c) {
                int k = half * 96 + c * 4;
                float4 v;
                if (n < N_NODES) {
                    if (k < 64) v = x4[(size_t)n * 16 + (k >> 2)];
                    else        v = agg4[(size_t)n * 32 + ((k - 64) >> 2)];
                } else v = make_float4(0.f, 0.f, 0.f, 0.f);
                ull hi, lo; split4(v, hi, lo);
                u32 off = (u32)(r * SBF + k) * 2;
                *(ull*)(Ah + off) = hi; *(ull*)(Al + off) = lo;
            }
        }
        __syncthreads();
        float acc[16][4];
        #pragma unroll
        for (int p = 0; p < 16; ++p) { acc[p][0]=0; acc[p][1]=0; acc[p][2]=0; acc[p][3]=0; }
        mma_loop<12, SBF>(aH, aL, bH, bL, acc);
        store_relu(acc, bs, out, tile * 128 + wid * 16, g, tq, N_NODES);
        __syncthreads();
    }
}

// ---------------- launch ----------------
extern "C" void kernel_launch(void* const* d_in, const int* in_sizes, int n_in,
                              void* d_out, int out_size)
{
    const float* x  = (const float*)d_in[0];
    const float* ea = (const float*)d_in[1];
    const int*   ei = (const int*)  d_in[2];
    const float* W1 = (const float*)d_in[3];
    const float* b1 = (const float*)d_in[4];
    const float* Wc = (const float*)d_in[5];
    const float* bc = (const float*)d_in[6];
    const float* W2 = (const float*)d_in[7];
    const float* b2 = (const float*)d_in[8];
    float* out = (float*)d_out;
    const int* row = ei;
    const int* col = ei + N_EDGES;

    void *p0,*p1,*p2,*p3,*pa,*pb,*pxw,*paw;
    cudaGetSymbolAddress(&p0, g_hhi); cudaGetSymbolAddress(&p1, g_hlo);
    cudaGetSymbolAddress(&p2, g_nhi); cudaGetSymbolAddress(&p3, g_nlo);
    cudaGetSymbolAddress(&pa, g_aggA); cudaGetSymbolAddress(&pb, g_aggB);
    cudaGetSymbolAddress(&pxw, g_xw);  cudaGetSymbolAddress(&paw, g_aggW);
    __nv_bfloat16* hhi = (__nv_bfloat16*)p0; __nv_bfloat16* hlo = (__nv_bfloat16*)p1;
    __nv_bfloat16* nhi = (__nv_bfloat16*)p2; __nv_bfloat16* nlo = (__nv_bfloat16*)p3;
    float* ain = (float*)pa; float* aout = (float*)pb;
    float* xw = (float*)pxw; float* aggW = (float*)paw;
    const size_t AGG_B = (size_t)N_NODES * HIDDEN * sizeof(float);
    const int NTN = (N_NODES + 127) / 128;   // 391

    cudaFuncSetAttribute(k_ngemm<64,72>,   cudaFuncAttributeMaxDynamicSharedMemorySize, 4*128*72*2);
    cudaFuncSetAttribute(k_ngemm<128,136>, cudaFuncAttributeMaxDynamicSharedMemorySize, 4*128*136*2);
    cudaFuncSetAttribute(k_init2,     cudaFuncAttributeMaxDynamicSharedMemorySize, I_TOT);
    cudaFuncSetAttribute(k_conv3<1>,  cudaFuncAttributeMaxDynamicSharedMemorySize, C3_TOT);
    cudaFuncSetAttribute(k_conv3<0>,  cudaFuncAttributeMaxDynamicSharedMemorySize, C3_TOT);
    cudaFuncSetAttribute(k_final_mma, cudaFuncAttributeMaxDynamicSharedMemorySize, FSM_TOT);

    // xW = x @ W1[0:64]; h0 = relu(ea @ W1[64:80] + xW[row] + b1), reds -> ain
    cudaMemsetAsync(ain, 0, AGG_B);
    k_ngemm<64,72><<<148, 256, 4*128*72*2>>>(x, W1, xw, N_NODES, NTN);
    k_init2<<<NT_E, 256, I_TOT>>>(ea, row, col, W1 + 64*128, b1, xw, hhi, hlo, ain);

    for (int d = 0; d < DEPTH; ++d) {
        const float* Wd = Wc + (size_t)d * HIDDEN * HIDDEN;
        k_ngemm<128,136><<<148, 256, 4*128*136*2>>>(ain, Wd, aggW, N_NODES, NTN);
        cudaMemsetAsync(aout, 0, AGG_B);
        if (d < DEPTH - 1)
            k_conv3<1><<<592, 256, C3_TOT>>>(hhi, hlo, row, col, Wd,
                                             bc + (size_t)d * HIDDEN, aggW, nhi, nlo, aout);
        else
            k_conv3<0><<<592, 256, C3_TOT>>>(hhi, hlo, row, col, Wd,
                                             bc + (size_t)d * HIDDEN, aggW, nhi, nlo, aout);
        __nv_bfloat16* t;
        t = hhi; hhi = nhi; nhi = t;
        t = hlo; hlo = nlo; nlo = t;
        float* f = ain; ain = aout; aout = f;
    }

    k_final_mma<<<148, 256, FSM_TOT>>>(x, ain, W2, b2, out);
}

// round 16
// speedup vs baseline: 1.0299x; 1.0299x over previous
#include <cuda_runtime.h>
#include <cuda_bf16.h>
#include <cstdint>

#define N_NODES 50000
#define N_EDGES 400000
#define HIDDEN 128
#define DEPTH 3
#define NT_E (N_EDGES / 128)          // 3125 (init tiles)
#define NT_C (N_EDGES / 64)           // 6250 (conv tiles)

typedef unsigned long long ull;
typedef uint32_t u32;

// ---------------- scratch ----------------
__device__ __nv_bfloat16 g_hhi[(size_t)N_EDGES * HIDDEN];
__device__ __nv_bfloat16 g_hlo[(size_t)N_EDGES * HIDDEN];
__device__ __nv_bfloat16 g_nhi[(size_t)N_EDGES * HIDDEN];
__device__ __nv_bfloat16 g_nlo[(size_t)N_EDGES * HIDDEN];
__device__ float g_aggA[(size_t)N_NODES * HIDDEN];
__device__ float g_aggB[(size_t)N_NODES * HIDDEN];
__device__ float g_xw  [(size_t)N_NODES * HIDDEN];
__device__ float g_aggW[(size_t)N_NODES * HIDDEN];

// ================= helpers =================
__device__ __forceinline__ u32 smem_u32(const void* p) {
    u32 a;
    asm("{ .reg .u64 t; cvta.to.shared.u64 t, %1; cvt.u32.u64 %0, t; }" : "=r"(a) : "l"(p));
    return a;
}

__device__ __forceinline__ void split4(float4 v, ull& hi, ull& lo) {
    __nv_bfloat16 h0 = __float2bfloat16_rn(v.x), h1 = __float2bfloat16_rn(v.y);
    __nv_bfloat16 h2 = __float2bfloat16_rn(v.z), h3 = __float2bfloat16_rn(v.w);
    __nv_bfloat16 l0 = __float2bfloat16_rn(v.x - __bfloat162float(h0));
    __nv_bfloat16 l1 = __float2bfloat16_rn(v.y - __bfloat162float(h1));
    __nv_bfloat16 l2 = __float2bfloat16_rn(v.z - __bfloat162float(h2));
    __nv_bfloat16 l3 = __float2bfloat16_rn(v.w - __bfloat162float(h3));
    u32 ha = (u32)__bfloat16_as_ushort(h0) | ((u32)__bfloat16_as_ushort(h1) << 16);
    u32 hb = (u32)__bfloat16_as_ushort(h2) | ((u32)__bfloat16_as_ushort(h3) << 16);
    u32 la = (u32)__bfloat16_as_ushort(l0) | ((u32)__bfloat16_as_ushort(l1) << 16);
    u32 lb = (u32)__bfloat16_as_ushort(l2) | ((u32)__bfloat16_as_ushort(l3) << 16);
    hi = (ull)ha | ((ull)hb << 32);
    lo = (ull)la | ((ull)lb << 32);
}

__device__ __forceinline__ void split2(float x, float y, u32& hi, u32& lo) {
    __nv_bfloat16 hx = __float2bfloat16_rn(x), hy = __float2bfloat16_rn(y);
    __nv_bfloat16 lx = __float2bfloat16_rn(x - __bfloat162float(hx));
    __nv_bfloat16 ly = __float2bfloat16_rn(y - __bfloat162float(hy));
    hi = (u32)__bfloat16_as_ushort(hx) | ((u32)__bfloat16_as_ushort(hy) << 16);
    lo = (u32)__bfloat16_as_ushort(lx) | ((u32)__bfloat16_as_ushort(ly) << 16);
}

__device__ __forceinline__ void ldsm4(u32* r, u32 addr) {
    asm volatile("ldmatrix.sync.aligned.m8n8.x4.shared.b16 {%0,%1,%2,%3}, [%4];"
                 : "=r"(r[0]), "=r"(r[1]), "=r"(r[2]), "=r"(r[3]) : "r"(addr));
}

__device__ __forceinline__ void mma16816(float* d, const u32* a, const u32* b) {
    asm volatile("mma.sync.aligned.m16n8k16.row.col.f32.bf16.bf16.f32 "
                 "{%0,%1,%2,%3}, {%4,%5,%6,%7}, {%8,%9}, {%0,%1,%2,%3};"
                 : "+f"(d[0]), "+f"(d[1]), "+f"(d[2]), "+f"(d[3])
                 : "r"(a[0]), "r"(a[1]), "r"(a[2]), "r"(a[3]), "r"(b[0]), "r"(b[1]));
}

__device__ __forceinline__ void cp16(u32 dst, const void* src) {
    asm volatile("cp.async.cg.shared.global [%0], [%1], 16;" :: "r"(dst), "l"(src));
}
#define CP_COMMIT() asm volatile("cp.async.commit_group;" ::: "memory")
#define CP_WAIT0()  asm volatile("cp.async.wait_group 0;" ::: "memory")

__device__ __forceinline__ void red2(float* p, float a, float b) {
    asm volatile("red.global.add.v2.f32 [%0], {%1, %2};" :: "l"(p), "f"(a), "f"(b) : "memory");
}

// generic 16-rows x 128-cols mainloop
template<int KSTEPS, int SBv>
__device__ __forceinline__ void mma_loop(u32 aH, u32 aL, u32 bH, u32 bL, float acc[16][4]) {
    for (int ks = 0; ks < KSTEPS; ++ks) {
        u32 ah[4], al[4];
        ldsm4(ah, aH + ks * 32);
        ldsm4(al, aL + ks * 32);
        #pragma unroll
        for (int p = 0; p < 8; ++p) {
            u32 bh[4], bl[4];
            ldsm4(bh, bH + p * (16 * SBv * 2) + ks * 32);
            ldsm4(bl, bL + p * (16 * SBv * 2) + ks * 32);
            mma16816(acc[2*p],   ah, bh);
            mma16816(acc[2*p+1], ah, bh + 2);
            mma16816(acc[2*p],   ah, bl);
            mma16816(acc[2*p+1], ah, bl + 2);
            mma16816(acc[2*p],   al, bh);
            mma16816(acc[2*p+1], al, bh + 2);
        }
    }
}

__device__ __forceinline__ void store_raw(const float acc[16][4], float* out,
                                          int row_base, int g, int tq, int rmax) {
    int r0 = row_base + g, r1 = row_base + g + 8;
    float* o0 = out + (size_t)r0 * 128;
    float* o1 = out + (size_t)r1 * 128;
    bool w0 = r0 < rmax, w1 = r1 < rmax;
    #pragma unroll
    for (int p = 0; p < 16; ++p) {
        int c0 = p * 8 + tq * 2;
        if (w0) *(float2*)(o0 + c0) = make_float2(acc[p][0], acc[p][1]);
        if (w1) *(float2*)(o1 + c0) = make_float2(acc[p][2], acc[p][3]);
    }
}

__device__ __forceinline__ void store_relu(const float acc[16][4], const float* bs,
                                           float* out, int row_base, int g, int tq, int rmax) {
    int r0 = row_base + g, r1 = row_base + g + 8;
    float* o0 = out + (size_t)r0 * 128;
    float* o1 = out + (size_t)r1 * 128;
    bool w0 = r0 < rmax, w1 = r1 < rmax;
    #pragma unroll
    for (int p = 0; p < 16; ++p) {
        int c0 = p * 8 + tq * 2;
        if (w0) *(float2*)(o0 + c0) = make_float2(fmaxf(acc[p][0] + bs[c0], 0.f),
                                                  fmaxf(acc[p][1] + bs[c0+1], 0.f));
        if (w1) *(float2*)(o1 + c0) = make_float2(fmaxf(acc[p][2] + bs[c0], 0.f),
                                                  fmaxf(acc[p][3] + bs[c0+1], 0.f));
    }
}

// ============ k_ngemm<KD,SBv>: persistent; out[M,128] = A[M,KD] @ W[KD,128] ============
template<int KD, int SBv>
__global__ __launch_bounds__(256) void k_ngemm(
    const float* __restrict__ A, const float* __restrict__ W,
    float* __restrict__ out, int M, int ntiles)
{
    extern __shared__ char smem[];
    const int M1 = 128 * SBv * 2;
    char* Ah = smem; char* Al = smem + M1; char* Bh = smem + 2*M1; char* Bl = smem + 3*M1;
    u32 sbase = smem_u32(smem);
    int tid = threadIdx.x, wid = tid >> 5, lane = tid & 31;
    int g = lane >> 2, tq = lane & 3;

    // W^T hi/lo: convert ONCE per CTA
    {
        int n = tid >> 1, half = tid & 1;
        #pragma unroll
        for (int c = 0; c < KD/8; ++c) {
            int k = half * (KD/2) + c * 4;
            float4 wv = make_float4(__ldg(&W[(k+0)*128 + n]), __ldg(&W[(k+1)*128 + n]),
                                    __ldg(&W[(k+2)*128 + n]), __ldg(&W[(k+3)*128 + n]));
            ull hi, lo; split4(wv, hi, lo);
            u32 off = (u32)(n * SBv + k) * 2;
            *(ull*)(Bh + off) = hi; *(ull*)(Bl + off) = lo;
        }
    }

    int a_row = lane & 15, a_col = (lane >> 4) * 8;
    u32 aH = sbase + (u32)((wid*16 + a_row) * SBv + a_col) * 2;
    u32 aL = aH + M1;
    int b_row = (lane & 7) + ((lane >> 4) & 1) * 8;
    int b_col = ((lane >> 3) & 1) * 8;
    u32 bH = sbase + 2*M1 + (u32)(b_row * SBv + b_col) * 2;
    u32 bL = bH + M1;

    for (int tile = blockIdx.x; tile < ntiles; tile += gridDim.x) {
        __syncthreads();   // previous MMA done reading A (also orders B conversion, iter 0)
        {
            int n = tid >> 1, half = tid & 1;
            int node = tile * 128 + n;
            #pragma unroll
            for (int c = 0; c < KD/8; ++c) {
                int k = half * (KD/2) + c * 4;
                float4 av = (node < M) ? *(const float4*)(A + (size_t)node * KD + k)
                                       : make_float4(0.f, 0.f, 0.f, 0.f);
                ull hi, lo; split4(av, hi, lo);
                u32 off = (u32)(n * SBv + k) * 2;
                *(ull*)(Ah + off) = hi; *(ull*)(Al + off) = lo;
            }
        }
        __syncthreads();

        float acc[16][4];
        #pragma unroll
        for (int p = 0; p < 16; ++p) { acc[p][0]=0; acc[p][1]=0; acc[p][2]=0; acc[p][3]=0; }
        mma_loop<KD/16, SBv>(aH, aL, bH, bL, acc);
        store_raw(acc, out, tile * 128 + wid * 16, g, tq, M);
    }
}

// ============ k_init2: h0 = relu(ea@W1b + xW[row] + b); writes bf16 hi/lo + reds ======
#define ISB 24
#define IMAT (128 * ISB * 2)
#define I_BIAS 0
#define I_A    512
#define I_B    (512 + 2*IMAT)
#define I_TOT  (512 + 4*IMAT)

__global__ __launch_bounds__(256) void k_init2(
    const float* __restrict__ ea, const int* __restrict__ row,
    const int* __restrict__ col,
    const float* __restrict__ Wb, const float* __restrict__ b,
    const float* __restrict__ xw,
    __nv_bfloat16* __restrict__ ohi, __nv_bfloat16* __restrict__ olo,
    float* __restrict__ aggn)
{
    extern __shared__ char smem[];
    u32 sbase = smem_u32(smem);
    int tid = threadIdx.x, wid = tid >> 5, lane = tid & 31;
    int g = lane >> 2, tq = lane & 3;
    int tile = blockIdx.x;

    int e0 = tile * 128 + wid * 16 + g;
    int e1 = e0 + 8;
    int r0i = __ldg(&row[e0]), r1i = __ldg(&row[e1]);
    int c0i = __ldg(&col[e0]), c1i = __ldg(&col[e1]);

    float* bs = (float*)(smem + I_BIAS);
    if (tid < 128) bs[tid] = __ldg(&b[tid]);
    {
        int n = tid >> 1, half = tid & 1;
        int e = tile * 128 + n;
        #pragma unroll
        for (int c = 0; c < 2; ++c) {
            int k = half * 8 + c * 4;
            float4 wv = make_float4(__ldg(&Wb[(k+0)*128 + n]), __ldg(&Wb[(k+1)*128 + n]),
                                    __ldg(&Wb[(k+2)*128 + n]), __ldg(&Wb[(k+3)*128 + n]));
            ull hi, lo; split4(wv, hi, lo);
            u32 off = (u32)(n * ISB + k) * 2;
            *(ull*)(smem + I_B + off) = hi; *(ull*)(smem + I_B + IMAT + off) = lo;
            float4 av = *(const float4*)(ea + (size_t)e * 16 + k);
            split4(av, hi, lo);
            *(ull*)(smem + I_A + off) = hi; *(ull*)(smem + I_A + IMAT + off) = lo;
        }
    }
    __syncthreads();

    int a_row = lane & 15, a_col = (lane >> 4) * 8;
    u32 aH = sbase + I_A + (u32)((wid*16 + a_row) * ISB + a_col) * 2;
    u32 aL = aH + IMAT;
    int b_row = (lane & 7) + ((lane >> 4) & 1) * 8;
    int b_col = ((lane >> 3) & 1) * 8;
    u32 bH = sbase + I_B + (u32)(b_row * ISB + b_col) * 2;
    u32 bL = bH + IMAT;

    float acc[16][4];
    #pragma unroll
    for (int p = 0; p < 16; ++p) { acc[p][0]=0; acc[p][1]=0; acc[p][2]=0; acc[p][3]=0; }
    mma_loop<1, ISB>(aH, aL, bH, bL, acc);

    const float* x0 = xw + (size_t)r0i * 128;
    const float* x1 = xw + (size_t)r1i * 128;
    float* ag0 = aggn + (size_t)c0i * 128;
    float* ag1 = aggn + (size_t)c1i * 128;
    u32* oh = (u32*)ohi; u32* ol = (u32*)olo;
    #pragma unroll
    for (int p = 0; p < 16; ++p) {
        int c = p * 8 + tq * 2;
        float2 g0 = __ldg((const float2*)(x0 + c));
        float2 g1 = __ldg((const float2*)(x1 + c));
        float v0x = fmaxf(acc[p][0] + g0.x + bs[c],   0.f);
        float v0y = fmaxf(acc[p][1] + g0.y + bs[c+1], 0.f);
        float v1x = fmaxf(acc[p][2] + g1.x + bs[c],   0.f);
        float v1y = fmaxf(acc[p][3] + g1.y + bs[c+1], 0.f);
        u32 hi, lo;
        split2(v0x, v0y, hi, lo);
        oh[(size_t)e0*64 + c/2] = hi; ol[(size_t)e0*64 + c/2] = lo;
        split2(v1x, v1y, hi, lo);
        oh[(size_t)e1*64 + c/2] = hi; ol[(size_t)e1*64 + c/2] = lo;
        red2(ag0 + c, v0x, v0y);
        red2(ag1 + c, v1x, v1y);
    }
}

// ============ k_conv2: 256-thr, 2 CTA/SM, 64-edge tiles, single-stage A (round-13) ======
#define CSB 136
#define CB_MAT (128 * CSB * 2)     // 34816 (B matrix, 128 n-rows)
#define CA_MAT (64 * CSB * 2)      // 17408 (A matrix, 64 edge-rows)
#define C2_BIAS 0
#define C2_B    512
#define C2_A    (512 + 2*CB_MAT)   // 70144
#define C2_TOT  (C2_A + 2*CA_MAT)  // 104960

template<int STORE_H>
__global__ __launch_bounds__(256, 2) void k_conv2(
    const __nv_bfloat16* __restrict__ hhi, const __nv_bfloat16* __restrict__ hlo,
    const int* __restrict__ row, const int* __restrict__ col,
    const float* __restrict__ W,
    const float* __restrict__ b, const float* __restrict__ aggW,
    __nv_bfloat16* __restrict__ ohi, __nv_bfloat16* __restrict__ olo,
    float* __restrict__ aggn)
{
    extern __shared__ char smem[];
    u32 sbase = smem_u32(smem);
    int tid = threadIdx.x, wid = tid >> 5, lane = tid & 31;
    int w_m = wid >> 1, w_n = wid & 1;
    int g = lane >> 2, tq = lane & 3;

    float* bs = (float*)(smem + C2_BIAS);
    if (tid < 128) bs[tid] = __ldg(&b[tid]);
    {   // B = W^T hi/lo (128 n-rows x 128 k)
        int n = tid >> 1, kh = (tid & 1) * 64;
        #pragma unroll
        for (int c = 0; c < 16; ++c) {
            int k = kh + c * 4;
            float4 wv = make_float4(__ldg(&W[(k+0)*128 + n]), __ldg(&W[(k+1)*128 + n]),
                                    __ldg(&W[(k+2)*128 + n]), __ldg(&W[(k+3)*128 + n]));
            ull hi, lo; split4(wv, hi, lo);
            u32 off = (u32)(n * CSB + k) * 2;
            *(ull*)(smem + C2_B + off) = hi; *(ull*)(smem + C2_B + CB_MAT + off) = lo;
        }
    }
    __syncthreads();

    int a_row = lane & 15, a_col = (lane >> 4) * 8;
    u32 aH = sbase + C2_A + (u32)((w_m*16 + a_row) * CSB + a_col) * 2;
    u32 aL = aH + CA_MAT;
    int b_row = (lane & 7) + ((lane >> 4) & 1) * 8;
    int b_col = ((lane >> 3) & 1) * 8;
    u32 b_base = sbase + C2_B + (u32)(b_row * CSB + b_col) * 2;

    int fr = tid >> 4, fc = tid & 15;   // 256 thr cover 16 rows x 16 col-chunks/pass

    // prologue: fill tile blockIdx.x
    int t = blockIdx.x;
    {
        #pragma unroll
        for (int k2 = 0; k2 < 4; ++k2) {
            int r = fr + k2 * 16;
            u32 d = sbase + C2_A + r * (CSB*2) + fc * 16;
            size_t go = ((size_t)(t * 64 + r)) * 128 + fc * 8;
            cp16(d, hhi + go);
            cp16(d + CA_MAT, hlo + go);
        }
    }
    CP_COMMIT();

    for (; t < NT_C; t += gridDim.x) {
        // epilogue prefetch (no smem dependency; lands under MMA)
        int e0 = t * 64 + w_m * 16 + g;
        int e1 = e0 + 8;
        int r0i = __ldg(&row[e0]), r1i = __ldg(&row[e1]);
        int c0i = __ldg(&col[e0]), c1i = __ldg(&col[e1]);
        const float2* aw0 = (const float2*)(aggW + (size_t)r0i * 128);
        const float2* aw1 = (const float2*)(aggW + (size_t)r1i * 128);
        float* ag0 = aggn + (size_t)c0i * 128;
        float* ag1 = aggn + (size_t)c1i * 128;
        float2 pg0[8], pg1[8];
        #pragma unroll
        for (int p = 0; p < 8; ++p) {
            int ci = w_n * 32 + p * 4 + tq;
            pg0[p] = __ldg(aw0 + ci);
            pg1[p] = __ldg(aw1 + ci);
        }

        CP_WAIT0();
        __syncthreads();

        // MMA: 16 rows x 64 cols (w_n half)
        float acc[8][4];
        #pragma unroll
        for (int p = 0; p < 8; ++p) { acc[p][0]=0; acc[p][1]=0; acc[p][2]=0; acc[p][3]=0; }
        for (int ks = 0; ks < 8; ++ks) {
            u32 ah[4], al[4];
            ldsm4(ah, aH + ks * 32);
            ldsm4(al, aL + ks * 32);
            #pragma unroll
            for (int p2 = 0; p2 < 4; ++p2) {
                u32 bh[4], bl[4];
                u32 ba = b_base + (u32)(w_n*64 + p2*16) * (CSB*2) + ks * 32;
                ldsm4(bh, ba);
                ldsm4(bl, ba + CB_MAT);
                mma16816(acc[2*p2],   ah, bh);
                mma16816(acc[2*p2+1], ah, bh + 2);
                mma16816(acc[2*p2],   ah, bl);
                mma16816(acc[2*p2+1], ah, bl + 2);
                mma16816(acc[2*p2],   al, bh);
                mma16816(acc[2*p2+1], al, bh + 2);
            }
        }

        __syncthreads();            // all warps done reading A stage

        // issue next fill (flies under epilogue + peer CTA)
        int tn = t + (int)gridDim.x;
        if (tn < NT_C) {
            #pragma unroll
            for (int k2 = 0; k2 < 4; ++k2) {
                int r = fr + k2 * 16;
                u32 d = sbase + C2_A + r * (CSB*2) + fc * 16;
                size_t go = ((size_t)(tn * 64 + r)) * 128 + fc * 8;
                cp16(d, hhi + go);
                cp16(d + CA_MAT, hlo + go);
            }
        }
        CP_COMMIT();

        // epilogue: h'[e] = relu(aggW[row[e]] - hW[e^1] + b); red into aggn
        u32* oh = (u32*)ohi; u32* ol = (u32*)olo;
        #pragma unroll
        for (int p = 0; p < 8; ++p) {
            int c = w_n * 64 + p * 8 + tq * 2;
            float r0x = __shfl_xor_sync(0xffffffffu, acc[p][0], 4);
            float r0y = __shfl_xor_sync(0xffffffffu, acc[p][1], 4);
            float r1x = __shfl_xor_sync(0xffffffffu, acc[p][2], 4);
            float r1y = __shfl_xor_sync(0xffffffffu, acc[p][3], 4);
            float v0x = fmaxf(pg0[p].x - r0x + bs[c],   0.f);
            float v0y = fmaxf(pg0[p].y - r0y + bs[c+1], 0.f);
            float v1x = fmaxf(pg1[p].x - r1x + bs[c],   0.f);
            float v1y = fmaxf(pg1[p].y - r1y + bs[c+1], 0.f);
            if (STORE_H) {
                u32 hi, lo;
                split2(v0x, v0y, hi, lo);
                oh[(size_t)e0*64 + c/2] = hi; ol[(size_t)e0*64 + c/2] = lo;
                split2(v1x, v1y, hi, lo);
                oh[(size_t)e1*64 + c/2] = hi; ol[(size_t)e1*64 + c/2] = lo;
            }
            red2(ag0 + c, v0x, v0y);
            red2(ag1 + c, v1x, v1y);
        }
    }
}

// ============ k_final: out = relu([x ; s] @ W2 + b2), K=192 ============
#define SBF 200
#define MATF (128 * SBF * 2)
#define FSM_BIAS 0
#define FSM_AHI  512
#define FSM_ALO  (FSM_AHI + MATF)
#define FSM_BHI  (FSM_ALO + MATF)
#define FSM_BLO  (FSM_BHI + MATF)
#define FSM_TOT  (FSM_BLO + MATF)

__global__ __launch_bounds__(256, 1) void k_final_mma(
    const float* __restrict__ x, const float* __restrict__ agg,
    const float* __restrict__ W, const float* __restrict__ b, float* __restrict__ out)
{
    extern __shared__ char smem[];
    u32 sbase = smem_u32(smem);
    int tid = threadIdx.x, wid = tid >> 5, lane = tid & 31;
    int g = lane >> 2, tq = lane & 3;

    float* bs = (float*)(smem + FSM_BIAS);
    if (tid < 128) bs[tid] = __ldg(&b[tid]);
    {
        int n = tid >> 1, kh = (tid & 1) * 96;
        char* Bh = smem + FSM_BHI; char* Bl = smem + FSM_BLO;
        #pragma unroll
        for (int c = 0; c < 24; ++c) {
            int k = kh + c * 4;
            float4 v = make_float4(__ldg(&W[(k+0)*128 + n]), __ldg(&W[(k+1)*128 + n]),
                                   __ldg(&W[(k+2)*128 + n]), __ldg(&W[(k+3)*128 + n]));
            ull hi, lo; split4(v, hi, lo);
            u32 off = (u32)(n * SBF + k) * 2;
            *(ull*)(Bh + off) = hi; *(ull*)(Bl + off) = lo;
        }
    }
    __syncthreads();

    int a_row = lane & 15, a_col = (lane >> 4) * 8;
    u32 aH = sbase + FSM_AHI + (u32)((wid * 16 + a_row) * SBF + a_col) * 2;
    u32 aL = aH + MATF;
    int b_row = (lane & 7) + ((lane >> 4) & 1) * 8;
    int b_col = ((lane >> 3) & 1) * 8;
    u32 bH = sbase + FSM_BHI + (u32)(b_row * SBF + b_col) * 2;
    u32 bL = bH + MATF;

    const float4* x4   = (const float4*)x;
    const float4* agg4 = (const float4*)agg;
    char* Ah = smem + FSM_AHI; char* Al = smem + FSM_ALO;
    const int NT = (N_NODES + 127) / 128;

    for (int tile = blockIdx.x; tile < NT; tile += gridDim.x) {
        {
            int r = tid >> 1, half = tid & 1;
            int n = tile * 128 + r;
            #pragma unroll
            for (int c = 0; c < 24; ++c) {
                int k = half * 96 + c * 4;
                float4 v;
                if (n < N_NODES) {
                    if (k < 64) v = x4[(size_t)n * 16 + (k >> 2)];
                    else        v = agg4[(size_t)n * 32 + ((k - 64) >> 2)];
                } else v = make_float4(0.f, 0.f, 0.f, 0.f);
                ull hi, lo; split4(v, hi, lo);
                u32 off = (u32)(r * SBF + k) * 2;
                *(ull*)(Ah + off) = hi; *(ull*)(Al + off) = lo;
            }
        }
        __syncthreads();
        float acc[16][4];
        #pragma unroll
        for (int p = 0; p < 16; ++p) { acc[p][0]=0; acc[p][1]=0; acc[p][2]=0; acc[p][3]=0; }
        mma_loop<12, SBF>(aH, aL, bH, bL, acc);
        store_relu(acc, bs, out, tile * 128 + wid * 16, g, tq, N_NODES);
        __syncthreads();
    }
}

// ---------------- launch ----------------
extern "C" void kernel_launch(void* const* d_in, const int* in_sizes, int n_in,
                              void* d_out, int out_size)
{
    const float* x  = (const float*)d_in[0];
    const float* ea = (const float*)d_in[1];
    const int*   ei = (const int*)  d_in[2];
    const float* W1 = (const float*)d_in[3];
    const float* b1 = (const float*)d_in[4];
    const float* Wc = (const float*)d_in[5];
    const float* bc = (const float*)d_in[6];
    const float* W2 = (const float*)d_in[7];
    const float* b2 = (const float*)d_in[8];
    float* out = (float*)d_out;
    const int* row = ei;
    const int* col = ei + N_EDGES;

    void *p0,*p1,*p2,*p3,*pa,*pb,*pxw,*paw;
    cudaGetSymbolAddress(&p0, g_hhi); cudaGetSymbolAddress(&p1, g_hlo);
    cudaGetSymbolAddress(&p2, g_nhi); cudaGetSymbolAddress(&p3, g_nlo);
    cudaGetSymbolAddress(&pa, g_aggA); cudaGetSymbolAddress(&pb, g_aggB);
    cudaGetSymbolAddress(&pxw, g_xw);  cudaGetSymbolAddress(&paw, g_aggW);
    __nv_bfloat16* hhi = (__nv_bfloat16*)p0; __nv_bfloat16* hlo = (__nv_bfloat16*)p1;
    __nv_bfloat16* nhi = (__nv_bfloat16*)p2; __nv_bfloat16* nlo = (__nv_bfloat16*)p3;
    float* ain = (float*)pa; float* aout = (float*)pb;
    float* xw = (float*)pxw; float* aggW = (float*)paw;
    const size_t AGG_B = (size_t)N_NODES * HIDDEN * sizeof(float);
    const int NTN = (N_NODES + 127) / 128;   // 391

    cudaFuncSetAttribute(k_ngemm<64,72>,   cudaFuncAttributeMaxDynamicSharedMemorySize, 4*128*72*2);
    cudaFuncSetAttribute(k_ngemm<128,136>, cudaFuncAttributeMaxDynamicSharedMemorySize, 4*128*136*2);
    cudaFuncSetAttribute(k_init2,     cudaFuncAttributeMaxDynamicSharedMemorySize, I_TOT);
    cudaFuncSetAttribute(k_conv2<1>,  cudaFuncAttributeMaxDynamicSharedMemorySize, C2_TOT);
    cudaFuncSetAttribute(k_conv2<0>,  cudaFuncAttributeMaxDynamicSharedMemorySize, C2_TOT);
    cudaFuncSetAttribute(k_final_mma, cudaFuncAttributeMaxDynamicSharedMemorySize, FSM_TOT);

    // xW = x @ W1[0:64]; h0 = relu(ea @ W1[64:80] + xW[row] + b1), reds -> ain
    cudaMemsetAsync(ain, 0, AGG_B);
    k_ngemm<64,72><<<148, 256, 4*128*72*2>>>(x, W1, xw, N_NODES, NTN);
    k_init2<<<NT_E, 256, I_TOT>>>(ea, row, col, W1 + 64*128, b1, xw, hhi, hlo, ain);

    for (int d = 0; d < DEPTH; ++d) {
        const float* Wd = Wc + (size_t)d * HIDDEN * HIDDEN;
        k_ngemm<128,136><<<148, 256, 4*128*136*2>>>(ain, Wd, aggW, N_NODES, NTN);
        cudaMemsetAsync(aout, 0, AGG_B);
        if (d < DEPTH - 1)
            k_conv2<1><<<296, 256, C2_TOT>>>(hhi, hlo, row, col, Wd,
                                             bc + (size_t)d * HIDDEN, aggW, nhi, nlo, aout);
        else
            k_conv2<0><<<296, 256, C2_TOT>>>(hhi, hlo, row, col, Wd,
                                             bc + (size_t)d * HIDDEN, aggW, nhi, nlo, aout);
        __nv_bfloat16* t;
        t = hhi; hhi = nhi; nhi = t;
        t = hlo; hlo = nlo; nlo = t;
        float* f = ain; ain = aout; aout = f;
    }

    k_final_mma<<<148, 256, FSM_TOT>>>(x, ain, W2, b2, out);
}

// round 17
// speedup vs baseline: 1.0411x; 1.0109x over previous
#include <cuda_runtime.h>
#include <cuda_bf16.h>
#include <cstdint>

#define N_NODES 50000
#define N_EDGES 400000
#define HIDDEN 128
#define DEPTH 3
#define NT_E (N_EDGES / 128)          // 3125 (init tiles)
#define NT_C (N_EDGES / 64)           // 6250 (conv tiles)

typedef unsigned long long ull;
typedef uint32_t u32;

// ---------------- scratch ----------------
__device__ __nv_bfloat16 g_hhi[(size_t)N_EDGES * HIDDEN];
__device__ __nv_bfloat16 g_hlo[(size_t)N_EDGES * HIDDEN];
__device__ __nv_bfloat16 g_nhi[(size_t)N_EDGES * HIDDEN];
__device__ __nv_bfloat16 g_nlo[(size_t)N_EDGES * HIDDEN];
__device__ float g_aggA[(size_t)N_NODES * HIDDEN];
__device__ float g_aggB[(size_t)N_NODES * HIDDEN];
__device__ float g_xw  [(size_t)N_NODES * HIDDEN];
__device__ float g_aggW[(size_t)N_NODES * HIDDEN];

// ================= helpers =================
__device__ __forceinline__ u32 smem_u32(const void* p) {
    u32 a;
    asm("{ .reg .u64 t; cvta.to.shared.u64 t, %1; cvt.u32.u64 %0, t; }" : "=r"(a) : "l"(p));
    return a;
}

__device__ __forceinline__ void split4(float4 v, ull& hi, ull& lo) {
    __nv_bfloat16 h0 = __float2bfloat16_rn(v.x), h1 = __float2bfloat16_rn(v.y);
    __nv_bfloat16 h2 = __float2bfloat16_rn(v.z), h3 = __float2bfloat16_rn(v.w);
    __nv_bfloat16 l0 = __float2bfloat16_rn(v.x - __bfloat162float(h0));
    __nv_bfloat16 l1 = __float2bfloat16_rn(v.y - __bfloat162float(h1));
    __nv_bfloat16 l2 = __float2bfloat16_rn(v.z - __bfloat162float(h2));
    __nv_bfloat16 l3 = __float2bfloat16_rn(v.w - __bfloat162float(h3));
    u32 ha = (u32)__bfloat16_as_ushort(h0) | ((u32)__bfloat16_as_ushort(h1) << 16);
    u32 hb = (u32)__bfloat16_as_ushort(h2) | ((u32)__bfloat16_as_ushort(h3) << 16);
    u32 la = (u32)__bfloat16_as_ushort(l0) | ((u32)__bfloat16_as_ushort(l1) << 16);
    u32 lb = (u32)__bfloat16_as_ushort(l2) | ((u32)__bfloat16_as_ushort(l3) << 16);
    hi = (ull)ha | ((ull)hb << 32);
    lo = (ull)la | ((ull)lb << 32);
}

__device__ __forceinline__ void split2(float x, float y, u32& hi, u32& lo) {
    __nv_bfloat16 hx = __float2bfloat16_rn(x), hy = __float2bfloat16_rn(y);
    __nv_bfloat16 lx = __float2bfloat16_rn(x - __bfloat162float(hx));
    __nv_bfloat16 ly = __float2bfloat16_rn(y - __bfloat162float(hy));
    hi = (u32)__bfloat16_as_ushort(hx) | ((u32)__bfloat16_as_ushort(hy) << 16);
    lo = (u32)__bfloat16_as_ushort(lx) | ((u32)__bfloat16_as_ushort(ly) << 16);
}

__device__ __forceinline__ void ldsm4(u32* r, u32 addr) {
    asm volatile("ldmatrix.sync.aligned.m8n8.x4.shared.b16 {%0,%1,%2,%3}, [%4];"
                 : "=r"(r[0]), "=r"(r[1]), "=r"(r[2]), "=r"(r[3]) : "r"(addr));
}

__device__ __forceinline__ void mma16816(float* d, const u32* a, const u32* b) {
    asm volatile("mma.sync.aligned.m16n8k16.row.col.f32.bf16.bf16.f32 "
                 "{%0,%1,%2,%3}, {%4,%5,%6,%7}, {%8,%9}, {%0,%1,%2,%3};"
                 : "+f"(d[0]), "+f"(d[1]), "+f"(d[2]), "+f"(d[3])
                 : "r"(a[0]), "r"(a[1]), "r"(a[2]), "r"(a[3]), "r"(b[0]), "r"(b[1]));
}

__device__ __forceinline__ void cp16(u32 dst, const void* src) {
    asm volatile("cp.async.cg.shared.global [%0], [%1], 16;" :: "r"(dst), "l"(src));
}
#define CP_COMMIT() asm volatile("cp.async.commit_group;" ::: "memory")
#define CP_WAIT0()  asm volatile("cp.async.wait_group 0;" ::: "memory")

__device__ __forceinline__ void red2(float* p, float a, float b) {
    asm volatile("red.global.add.v2.f32 [%0], {%1, %2};" :: "l"(p), "f"(a), "f"(b) : "memory");
}

// generic 16-rows x 128-cols mainloop
template<int KSTEPS, int SBv>
__device__ __forceinline__ void mma_loop(u32 aH, u32 aL, u32 bH, u32 bL, float acc[16][4]) {
    for (int ks = 0; ks < KSTEPS; ++ks) {
        u32 ah[4], al[4];
        ldsm4(ah, aH + ks * 32);
        ldsm4(al, aL + ks * 32);
        #pragma unroll
        for (int p = 0; p < 8; ++p) {
            u32 bh[4], bl[4];
            ldsm4(bh, bH + p * (16 * SBv * 2) + ks * 32);
            ldsm4(bl, bL + p * (16 * SBv * 2) + ks * 32);
            mma16816(acc[2*p],   ah, bh);
            mma16816(acc[2*p+1], ah, bh + 2);
            mma16816(acc[2*p],   ah, bl);
            mma16816(acc[2*p+1], ah, bl + 2);
            mma16816(acc[2*p],   al, bh);
            mma16816(acc[2*p+1], al, bh + 2);
        }
    }
}

__device__ __forceinline__ void store_raw(const float acc[16][4], float* out,
                                          int row_base, int g, int tq, int rmax) {
    int r0 = row_base + g, r1 = row_base + g + 8;
    float* o0 = out + (size_t)r0 * 128;
    float* o1 = out + (size_t)r1 * 128;
    bool w0 = r0 < rmax, w1 = r1 < rmax;
    #pragma unroll
    for (int p = 0; p < 16; ++p) {
        int c0 = p * 8 + tq * 2;
        if (w0) *(float2*)(o0 + c0) = make_float2(acc[p][0], acc[p][1]);
        if (w1) *(float2*)(o1 + c0) = make_float2(acc[p][2], acc[p][3]);
    }
}

__device__ __forceinline__ void store_relu(const float acc[16][4], const float* bs,
                                           float* out, int row_base, int g, int tq, int rmax) {
    int r0 = row_base + g, r1 = row_base + g + 8;
    float* o0 = out + (size_t)r0 * 128;
    float* o1 = out + (size_t)r1 * 128;
    bool w0 = r0 < rmax, w1 = r1 < rmax;
    #pragma unroll
    for (int p = 0; p < 16; ++p) {
        int c0 = p * 8 + tq * 2;
        if (w0) *(float2*)(o0 + c0) = make_float2(fmaxf(acc[p][0] + bs[c0], 0.f),
                                                  fmaxf(acc[p][1] + bs[c0+1], 0.f));
        if (w1) *(float2*)(o1 + c0) = make_float2(fmaxf(acc[p][2] + bs[c0], 0.f),
                                                  fmaxf(acc[p][3] + bs[c0+1], 0.f));
    }
}

// ============ k_ngemm<KD,SBv>: persistent; out = A @ W; also zeroes zbuf ============
template<int KD, int SBv>
__global__ __launch_bounds__(256) void k_ngemm(
    const float* __restrict__ A, const float* __restrict__ W,
    float* __restrict__ out, int M, int ntiles, float* __restrict__ zbuf)
{
    extern __shared__ char smem[];
    const int M1 = 128 * SBv * 2;
    char* Ah = smem; char* Al = smem + M1; char* Bh = smem + 2*M1; char* Bl = smem + 3*M1;
    u32 sbase = smem_u32(smem);
    int tid = threadIdx.x, wid = tid >> 5, lane = tid & 31;
    int g = lane >> 2, tq = lane & 3;

    // zero the next agg buffer (replaces cudaMemsetAsync; completes before kernel end,
    // and the consumer (reds) is a later kernel in stream order)
    {
        float4* z4 = (float4*)zbuf;
        const int ZN = N_NODES * HIDDEN / 4;
        for (int i = blockIdx.x * 256 + tid; i < ZN; i += gridDim.x * 256)
            z4[i] = make_float4(0.f, 0.f, 0.f, 0.f);
    }

    // W^T hi/lo: convert ONCE per CTA
    {
        int n = tid >> 1, half = tid & 1;
        #pragma unroll
        for (int c = 0; c < KD/8; ++c) {
            int k = half * (KD/2) + c * 4;
            float4 wv = make_float4(__ldg(&W[(k+0)*128 + n]), __ldg(&W[(k+1)*128 + n]),
                                    __ldg(&W[(k+2)*128 + n]), __ldg(&W[(k+3)*128 + n]));
            ull hi, lo; split4(wv, hi, lo);
            u32 off = (u32)(n * SBv + k) * 2;
            *(ull*)(Bh + off) = hi; *(ull*)(Bl + off) = lo;
        }
    }

    int a_row = lane & 15, a_col = (lane >> 4) * 8;
    u32 aH = sbase + (u32)((wid*16 + a_row) * SBv + a_col) * 2;
    u32 aL = aH + M1;
    int b_row = (lane & 7) + ((lane >> 4) & 1) * 8;
    int b_col = ((lane >> 3) & 1) * 8;
    u32 bH = sbase + 2*M1 + (u32)(b_row * SBv + b_col) * 2;
    u32 bL = bH + M1;

    for (int tile = blockIdx.x; tile < ntiles; tile += gridDim.x) {
        __syncthreads();   // previous MMA done reading A (also orders B conversion, iter 0)
        {
            int n = tid >> 1, half = tid & 1;
            int node = tile * 128 + n;
            #pragma unroll
            for (int c = 0; c < KD/8; ++c) {
                int k = half * (KD/2) + c * 4;
                float4 av = (node < M) ? *(const float4*)(A + (size_t)node * KD + k)
                                       : make_float4(0.f, 0.f, 0.f, 0.f);
                ull hi, lo; split4(av, hi, lo);
                u32 off = (u32)(n * SBv + k) * 2;
                *(ull*)(Ah + off) = hi; *(ull*)(Al + off) = lo;
            }
        }
        __syncthreads();

        float acc[16][4];
        #pragma unroll
        for (int p = 0; p < 16; ++p) { acc[p][0]=0; acc[p][1]=0; acc[p][2]=0; acc[p][3]=0; }
        mma_loop<KD/16, SBv>(aH, aL, bH, bL, acc);
        store_raw(acc, out, tile * 128 + wid * 16, g, tq, M);
    }
}

// ============ k_init2: h0 = relu(ea@W1b + xW[row] + b); writes bf16 hi/lo + reds ======
#define ISB 24
#define IMAT (128 * ISB * 2)
#define I_BIAS 0
#define I_A    512
#define I_B    (512 + 2*IMAT)
#define I_TOT  (512 + 4*IMAT)

__global__ __launch_bounds__(256) void k_init2(
    const float* __restrict__ ea, const int* __restrict__ row,
    const int* __restrict__ col,
    const float* __restrict__ Wb, const float* __restrict__ b,
    const float* __restrict__ xw,
    __nv_bfloat16* __restrict__ ohi, __nv_bfloat16* __restrict__ olo,
    float* __restrict__ aggn)
{
    extern __shared__ char smem[];
    u32 sbase = smem_u32(smem);
    int tid = threadIdx.x, wid = tid >> 5, lane = tid & 31;
    int g = lane >> 2, tq = lane & 3;
    int tile = blockIdx.x;

    int e0 = tile * 128 + wid * 16 + g;
    int e1 = e0 + 8;
    int r0i = __ldg(&row[e0]), r1i = __ldg(&row[e1]);
    int c0i = __ldg(&col[e0]), c1i = __ldg(&col[e1]);

    float* bs = (float*)(smem + I_BIAS);
    if (tid < 128) bs[tid] = __ldg(&b[tid]);
    {
        int n = tid >> 1, half = tid & 1;
        int e = tile * 128 + n;
        #pragma unroll
        for (int c = 0; c < 2; ++c) {
            int k = half * 8 + c * 4;
            float4 wv = make_float4(__ldg(&Wb[(k+0)*128 + n]), __ldg(&Wb[(k+1)*128 + n]),
                                    __ldg(&Wb[(k+2)*128 + n]), __ldg(&Wb[(k+3)*128 + n]));
            ull hi, lo; split4(wv, hi, lo);
            u32 off = (u32)(n * ISB + k) * 2;
            *(ull*)(smem + I_B + off) = hi; *(ull*)(smem + I_B + IMAT + off) = lo;
            float4 av = *(const float4*)(ea + (size_t)e * 16 + k);
            split4(av, hi, lo);
            *(ull*)(smem + I_A + off) = hi; *(ull*)(smem + I_A + IMAT + off) = lo;
        }
    }
    __syncthreads();

    int a_row = lane & 15, a_col = (lane >> 4) * 8;
    u32 aH = sbase + I_A + (u32)((wid*16 + a_row) * ISB + a_col) * 2;
    u32 aL = aH + IMAT;
    int b_row = (lane & 7) + ((lane >> 4) & 1) * 8;
    int b_col = ((lane >> 3) & 1) * 8;
    u32 bH = sbase + I_B + (u32)(b_row * ISB + b_col) * 2;
    u32 bL = bH + IMAT;

    float acc[16][4];
    #pragma unroll
    for (int p = 0; p < 16; ++p) { acc[p][0]=0; acc[p][1]=0; acc[p][2]=0; acc[p][3]=0; }
    mma_loop<1, ISB>(aH, aL, bH, bL, acc);

    const float* x0 = xw + (size_t)r0i * 128;
    const float* x1 = xw + (size_t)r1i * 128;
    float* ag0 = aggn + (size_t)c0i * 128;
    float* ag1 = aggn + (size_t)c1i * 128;
    u32* oh = (u32*)ohi; u32* ol = (u32*)olo;
    #pragma unroll
    for (int p = 0; p < 16; ++p) {
        int c = p * 8 + tq * 2;
        float2 g0 = __ldg((const float2*)(x0 + c));
        float2 g1 = __ldg((const float2*)(x1 + c));
        float v0x = fmaxf(acc[p][0] + g0.x + bs[c],   0.f);
        float v0y = fmaxf(acc[p][1] + g0.y + bs[c+1], 0.f);
        float v1x = fmaxf(acc[p][2] + g1.x + bs[c],   0.f);
        float v1y = fmaxf(acc[p][3] + g1.y + bs[c+1], 0.f);
        u32 hi, lo;
        split2(v0x, v0y, hi, lo);
        oh[(size_t)e0*64 + c/2] = hi; ol[(size_t)e0*64 + c/2] = lo;
        split2(v1x, v1y, hi, lo);
        oh[(size_t)e1*64 + c/2] = hi; ol[(size_t)e1*64 + c/2] = lo;
        red2(ag0 + c, v0x, v0y);
        red2(ag1 + c, v1x, v1y);
    }
}

// ============ k_conv2: 256-thr, 2 CTA/SM, 64-edge tiles, single-stage A (round-13) ======
#define CSB 136
#define CB_MAT (128 * CSB * 2)     // 34816 (B matrix, 128 n-rows)
#define CA_MAT (64 * CSB * 2)      // 17408 (A matrix, 64 edge-rows)
#define C2_BIAS 0
#define C2_B    512
#define C2_A    (512 + 2*CB_MAT)   // 70144
#define C2_TOT  (C2_A + 2*CA_MAT)  // 104960

template<int STORE_H>
__global__ __launch_bounds__(256, 2) void k_conv2(
    const __nv_bfloat16* __restrict__ hhi, const __nv_bfloat16* __restrict__ hlo,
    const int* __restrict__ row, const int* __restrict__ col,
    const float* __restrict__ W,
    const float* __restrict__ b, const float* __restrict__ aggW,
    __nv_bfloat16* __restrict__ ohi, __nv_bfloat16* __restrict__ olo,
    float* __restrict__ aggn)
{
    extern __shared__ char smem[];
    u32 sbase = smem_u32(smem);
    int tid = threadIdx.x, wid = tid >> 5, lane = tid & 31;
    int w_m = wid >> 1, w_n = wid & 1;
    int g = lane >> 2, tq = lane & 3;

    float* bs = (float*)(smem + C2_BIAS);
    if (tid < 128) bs[tid] = __ldg(&b[tid]);
    {   // B = W^T hi/lo (128 n-rows x 128 k)
        int n = tid >> 1, kh = (tid & 1) * 64;
        #pragma unroll
        for (int c = 0; c < 16; ++c) {
            int k = kh + c * 4;
            float4 wv = make_float4(__ldg(&W[(k+0)*128 + n]), __ldg(&W[(k+1)*128 + n]),
                                    __ldg(&W[(k+2)*128 + n]), __ldg(&W[(k+3)*128 + n]));
            ull hi, lo; split4(wv, hi, lo);
            u32 off = (u32)(n * CSB + k) * 2;
            *(ull*)(smem + C2_B + off) = hi; *(ull*)(smem + C2_B + CB_MAT + off) = lo;
        }
    }
    __syncthreads();

    int a_row = lane & 15, a_col = (lane >> 4) * 8;
    u32 aH = sbase + C2_A + (u32)((w_m*16 + a_row) * CSB + a_col) * 2;
    u32 aL = aH + CA_MAT;
    int b_row = (lane & 7) + ((lane >> 4) & 1) * 8;
    int b_col = ((lane >> 3) & 1) * 8;
    u32 b_base = sbase + C2_B + (u32)(b_row * CSB + b_col) * 2;

    int fr = tid >> 4, fc = tid & 15;   // 256 thr cover 16 rows x 16 col-chunks/pass

    // prologue: fill tile blockIdx.x
    int t = blockIdx.x;
    {
        #pragma unroll
        for (int k2 = 0; k2 < 4; ++k2) {
            int r = fr + k2 * 16;
            u32 d = sbase + C2_A + r * (CSB*2) + fc * 16;
            size_t go = ((size_t)(t * 64 + r)) * 128 + fc * 8;
            cp16(d, hhi + go);
            cp16(d + CA_MAT, hlo + go);
        }
    }
    CP_COMMIT();

    for (; t < NT_C; t += gridDim.x) {
        // epilogue prefetch (no smem dependency; lands under MMA)
        int e0 = t * 64 + w_m * 16 + g;
        int e1 = e0 + 8;
        int r0i = __ldg(&row[e0]), r1i = __ldg(&row[e1]);
        int c0i = __ldg(&col[e0]), c1i = __ldg(&col[e1]);
        const float2* aw0 = (const float2*)(aggW + (size_t)r0i * 128);
        const float2* aw1 = (const float2*)(aggW + (size_t)r1i * 128);
        float* ag0 = aggn + (size_t)c0i * 128;
        float* ag1 = aggn + (size_t)c1i * 128;
        float2 pg0[8], pg1[8];
        #pragma unroll
        for (int p = 0; p < 8; ++p) {
            int ci = w_n * 32 + p * 4 + tq;
            pg0[p] = __ldg(aw0 + ci);
            pg1[p] = __ldg(aw1 + ci);
        }

        CP_WAIT0();
        __syncthreads();

        // MMA: 16 rows x 64 cols (w_n half)
        float acc[8][4];
        #pragma unroll
        for (int p = 0; p < 8; ++p) { acc[p][0]=0; acc[p][1]=0; acc[p][2]=0; acc[p][3]=0; }
        for (int ks = 0; ks < 8; ++ks) {
            u32 ah[4], al[4];
            ldsm4(ah, aH + ks * 32);
            ldsm4(al, aL + ks * 32);
            #pragma unroll
            for (int p2 = 0; p2 < 4; ++p2) {
                u32 bh[4], bl[4];
                u32 ba = b_base + (u32)(w_n*64 + p2*16) * (CSB*2) + ks * 32;
                ldsm4(bh, ba);
                ldsm4(bl, ba + CB_MAT);
                mma16816(acc[2*p2],   ah, bh);
                mma16816(acc[2*p2+1], ah, bh + 2);
                mma16816(acc[2*p2],   ah, bl);
                mma16816(acc[2*p2+1], ah, bl + 2);
                mma16816(acc[2*p2],   al, bh);
                mma16816(acc[2*p2+1], al, bh + 2);
            }
        }

        __syncthreads();            // all warps done reading A stage

        // issue next fill (flies under epilogue + peer CTA)
        int tn = t + (int)gridDim.x;
        if (tn < NT_C) {
            #pragma unroll
            for (int k2 = 0; k2 < 4; ++k2) {
                int r = fr + k2 * 16;
                u32 d = sbase + C2_A + r * (CSB*2) + fc * 16;
                size_t go = ((size_t)(tn * 64 + r)) * 128 + fc * 8;
                cp16(d, hhi + go);
                cp16(d + CA_MAT, hlo + go);
            }
        }
        CP_COMMIT();

        // epilogue: h'[e] = relu(aggW[row[e]] - hW[e^1] + b); red into aggn
        u32* oh = (u32*)ohi; u32* ol = (u32*)olo;
        #pragma unroll
        for (int p = 0; p < 8; ++p) {
            int c = w_n * 64 + p * 8 + tq * 2;
            float r0x = __shfl_xor_sync(0xffffffffu, acc[p][0], 4);
            float r0y = __shfl_xor_sync(0xffffffffu, acc[p][1], 4);
            float r1x = __shfl_xor_sync(0xffffffffu, acc[p][2], 4);
            float r1y = __shfl_xor_sync(0xffffffffu, acc[p][3], 4);
            float v0x = fmaxf(pg0[p].x - r0x + bs[c],   0.f);
            float v0y = fmaxf(pg0[p].y - r0y + bs[c+1], 0.f);
            float v1x = fmaxf(pg1[p].x - r1x + bs[c],   0.f);
            float v1y = fmaxf(pg1[p].y - r1y + bs[c+1], 0.f);
            if (STORE_H) {
                u32 hi, lo;
                split2(v0x, v0y, hi, lo);
                oh[(size_t)e0*64 + c/2] = hi; ol[(size_t)e0*64 + c/2] = lo;
                split2(v1x, v1y, hi, lo);
                oh[(size_t)e1*64 + c/2] = hi; ol[(size_t)e1*64 + c/2] = lo;
            }
            red2(ag0 + c, v0x, v0y);
            red2(ag1 + c, v1x, v1y);
        }
    }
}

// ============ k_final: out = relu([x ; s] @ W2 + b2), K=192 ============
#define SBF 200
#define MATF (128 * SBF * 2)
#define FSM_BIAS 0
#define FSM_AHI  512
#define FSM_ALO  (FSM_AHI + MATF)
#define FSM_BHI  (FSM_ALO + MATF)
#define FSM_BLO  (FSM_BHI + MATF)
#define FSM_TOT  (FSM_BLO + MATF)

__global__ __launch_bounds__(256, 1) void k_final_mma(
    const float* __restrict__ x, const float* __restrict__ agg,
    const float* __restrict__ W, const float* __restrict__ b, float* __restrict__ out)
{
    extern __shared__ char smem[];
    u32 sbase = smem_u32(smem);
    int tid = threadIdx.x, wid = tid >> 5, lane = tid & 31;
    int g = lane >> 2, tq = lane & 3;

    float* bs = (float*)(smem + FSM_BIAS);
    if (tid < 128) bs[tid] = __ldg(&b[tid]);
    {
        int n = tid >> 1, kh = (tid & 1) * 96;
        char* Bh = smem + FSM_BHI; char* Bl = smem + FSM_BLO;
        #pragma unroll
        for (int c = 0; c < 24; ++c) {
            int k = kh + c * 4;
            float4 v = make_float4(__ldg(&W[(k+0)*128 + n]), __ldg(&W[(k+1)*128 + n]),
                                   __ldg(&W[(k+2)*128 + n]), __ldg(&W[(k+3)*128 + n]));
            ull hi, lo; split4(v, hi, lo);
            u32 off = (u32)(n * SBF + k) * 2;
            *(ull*)(Bh + off) = hi; *(ull*)(Bl + off) = lo;
        }
    }
    __syncthreads();

    int a_row = lane & 15, a_col = (lane >> 4) * 8;
    u32 aH = sbase + FSM_AHI + (u32)((wid * 16 + a_row) * SBF + a_col) * 2;
    u32 aL = aH + MATF;
    int b_row = (lane & 7) + ((lane >> 4) & 1) * 8;
    int b_col = ((lane >> 3) & 1) * 8;
    u32 bH = sbase + FSM_BHI + (u32)(b_row * SBF + b_col) * 2;
    u32 bL = bH + MATF;

    const float4* x4   = (const float4*)x;
    const float4* agg4 = (const float4*)agg;
    char* Ah = smem + FSM_AHI; char* Al = smem + FSM_ALO;
    const int NT = (N_NODES + 127) / 128;

    for (int tile = blockIdx.x; tile < NT; tile += gridDim.x) {
        {
            int r = tid >> 1, half = tid & 1;
            int n = tile * 128 + r;
            #pragma unroll
            for (int c = 0; c < 24; ++c) {
                int k = half * 96 + c * 4;
                float4 v;
                if (n < N_NODES) {
                    if (k < 64) v = x4[(size_t)n * 16 + (k >> 2)];
                    else        v = agg4[(size_t)n * 32 + ((k - 64) >> 2)];
                } else v = make_float4(0.f, 0.f, 0.f, 0.f);
                ull hi, lo; split4(v, hi, lo);
                u32 off = (u32)(r * SBF + k) * 2;
                *(ull*)(Ah + off) = hi; *(ull*)(Al + off) = lo;
            }
        }
        __syncthreads();
        float acc[16][4];
        #pragma unroll
        for (int p = 0; p < 16; ++p) { acc[p][0]=0; acc[p][1]=0; acc[p][2]=0; acc[p][3]=0; }
        mma_loop<12, SBF>(aH, aL, bH, bL, acc);
        store_relu(acc, bs, out, tile * 128 + wid * 16, g, tq, N_NODES);
        __syncthreads();
    }
}

// ---------------- launch ----------------
extern "C" void kernel_launch(void* const* d_in, const int* in_sizes, int n_in,
                              void* d_out, int out_size)
{
    const float* x  = (const float*)d_in[0];
    const float* ea = (const float*)d_in[1];
    const int*   ei = (const int*)  d_in[2];
    const float* W1 = (const float*)d_in[3];
    const float* b1 = (const float*)d_in[4];
    const float* Wc = (const float*)d_in[5];
    const float* bc = (const float*)d_in[6];
    const float* W2 = (const float*)d_in[7];
    const float* b2 = (const float*)d_in[8];
    float* out = (float*)d_out;
    const int* row = ei;
    const int* col = ei + N_EDGES;

    void *p0,*p1,*p2,*p3,*pa,*pb,*pxw,*paw;
    cudaGetSymbolAddress(&p0, g_hhi); cudaGetSymbolAddress(&p1, g_hlo);
    cudaGetSymbolAddress(&p2, g_nhi); cudaGetSymbolAddress(&p3, g_nlo);
    cudaGetSymbolAddress(&pa, g_aggA); cudaGetSymbolAddress(&pb, g_aggB);
    cudaGetSymbolAddress(&pxw, g_xw);  cudaGetSymbolAddress(&paw, g_aggW);
    __nv_bfloat16* hhi = (__nv_bfloat16*)p0; __nv_bfloat16* hlo = (__nv_bfloat16*)p1;
    __nv_bfloat16* nhi = (__nv_bfloat16*)p2; __nv_bfloat16* nlo = (__nv_bfloat16*)p3;
    float* ain = (float*)pa; float* aout = (float*)pb;
    float* xw = (float*)pxw; float* aggW = (float*)paw;
    const int NTN = (N_NODES + 127) / 128;   // 391

    cudaFuncSetAttribute(k_ngemm<64,72>,   cudaFuncAttributeMaxDynamicSharedMemorySize, 4*128*72*2);
    cudaFuncSetAttribute(k_ngemm<128,136>, cudaFuncAttributeMaxDynamicSharedMemorySize, 4*128*136*2);
    cudaFuncSetAttribute(k_init2,     cudaFuncAttributeMaxDynamicSharedMemorySize, I_TOT);
    cudaFuncSetAttribute(k_conv2<1>,  cudaFuncAttributeMaxDynamicSharedMemorySize, C2_TOT);
    cudaFuncSetAttribute(k_conv2<0>,  cudaFuncAttributeMaxDynamicSharedMemorySize, C2_TOT);
    cudaFuncSetAttribute(k_final_mma, cudaFuncAttributeMaxDynamicSharedMemorySize, FSM_TOT);

    // ngemm<64> computes xW AND zeroes ain (consumed by init2's reds, next launch)
    k_ngemm<64,72><<<148, 256, 4*128*72*2>>>(x, W1, xw, N_NODES, NTN, ain);
    k_init2<<<NT_E, 256, I_TOT>>>(ea, row, col, W1 + 64*128, b1, xw, hhi, hlo, ain);

    for (int d = 0; d < DEPTH; ++d) {
        const float* Wd = Wc + (size_t)d * HIDDEN * HIDDEN;
        // ngemm<128> computes aggW from ain AND zeroes aout (consumed by conv's reds)
        k_ngemm<128,136><<<148, 256, 4*128*136*2>>>(ain, Wd, aggW, N_NODES, NTN, aout);
        if (d < DEPTH - 1)
            k_conv2<1><<<296, 256, C2_TOT>>>(hhi, hlo, row, col, Wd,
                                             bc + (size_t)d * HIDDEN, aggW, nhi, nlo, aout);
        else
            k_conv2<0><<<296, 256, C2_TOT>>>(hhi, hlo, row, col, Wd,
                                             bc + (size_t)d * HIDDEN, aggW, nhi, nlo, aout);
        __nv_bfloat16* t;
        t = hhi; hhi = nhi; nhi = t;
        t = hlo; hlo = nlo; nlo = t;
        float* f = ain; ain = aout; aout = f;
    }

    k_final_mma<<<148, 256, FSM_TOT>>>(x, ain, W2, b2, out);
}